// round 3
// baseline (speedup 1.0000x reference)
#include <cuda_runtime.h>

#define NB 16
#define SECL 16
#define WORDL 256
#define SLEN 4096
#define DIM 1024
#define FSZ 2
#define GATH (FSZ*WORDL)   // 512
#define NPART 16           // k5 context partials

// ---------------- scratch (device globals; no allocation) ----------------
__device__ float g_decfeat[NB*DIM];
__device__ float g_scores[NB*GATH];
__device__ float g_attn[NB*GATH];
__device__ float g_ctxpart[NPART*NB*DIM];

// accurate tanh: 1 - 2/(e^{2x}+1), ex2/rcp MUFU (~1e-7 abs error)
__device__ __forceinline__ float fast_tanh(float x) {
    float e;
    asm("ex2.approx.f32 %0, %1;" : "=f"(e) : "f"(x * 2.8853900817779268f)); // 2*log2(e)
    float r;
    asm("rcp.approx.f32 %0, %1;" : "=f"(r) : "f"(e + 1.0f));
    return 1.0f - 2.0f * r;
}

// top-2 of focus[b] (jax first-occurrence tie rule); serial, run by ONE thread
__device__ __forceinline__ void top2_focus(const float* __restrict__ focus, int b,
                                           int& i0, int& i1, float& v0, float& v1) {
    const float* f = focus + b*SECL;
    v0 = -__int_as_float(0x7f800000); i0 = 0;
#pragma unroll
    for (int j = 0; j < SECL; j++) { float x = __ldg(&f[j]); if (x > v0) { v0 = x; i0 = j; } }
    v1 = -__int_as_float(0x7f800000); i1 = 0;
#pragma unroll
    for (int j = 0; j < SECL; j++) {
        if (j == i0) continue;
        float x = __ldg(&f[j]); if (x > v1) { v1 = x; i1 = j; }
    }
}

// ---------------- K1: dec_feature = dec_hidden @ W_dec^T + b_dec ----------------
__global__ __launch_bounds__(256) void k1_decproj(const float* __restrict__ h,
                                                  const float* __restrict__ W,
                                                  const float* __restrict__ bvec) {
    int warp = threadIdx.x >> 5;
    int lane = threadIdx.x & 31;
    int d = blockIdx.x*8 + warp;
    const float4* Wd = (const float4*)(W + (size_t)d*DIM);
    const float4* h4 = (const float4*)h;
    float acc[NB];
#pragma unroll
    for (int b = 0; b < NB; b++) acc[b] = 0.f;
#pragma unroll
    for (int i = 0; i < 8; i++) {
        int kk = lane + i*32;
        float4 w = __ldg(&Wd[kk]);
#pragma unroll
        for (int b = 0; b < NB; b++) {
            float4 hb = __ldg(&h4[b*256 + kk]);
            acc[b] = fmaf(w.x, hb.x, fmaf(w.y, hb.y, fmaf(w.z, hb.z, fmaf(w.w, hb.w, acc[b]))));
        }
    }
#pragma unroll
    for (int b = 0; b < NB; b++) {
#pragma unroll
        for (int o = 16; o > 0; o >>= 1)
            acc[b] += __shfl_xor_sync(0xffffffffu, acc[b], o);
    }
    if (lane == 0) {
        float bd = bvec[d];
#pragma unroll
        for (int b = 0; b < NB; b++)
            g_decfeat[b*DIM + d] = acc[b] + bd;
    }
}

// ---------------- K3: scores on gathered sections only ----------------
// one warp per gathered position; 1024 blocks * 256 threads (8 warps = 8 rows, same b)
__global__ __launch_bounds__(256) void k3_scores(const float* __restrict__ enc_feature,
                                                 const float* __restrict__ coverage,
                                                 const float* __restrict__ vvec,
                                                 const float* __restrict__ w_cov,
                                                 const float* __restrict__ focus) {
    __shared__ int sh_sec[2];
    int warp = threadIdx.x >> 5;
    int lane = threadIdx.x & 31;
    int gw = blockIdx.x*8 + warp;
    int b = gw >> 9;
    int r = gw & 511;
    if (threadIdx.x == 0) {
        int i0, i1; float v0, v1;
        top2_focus(focus, b, i0, i1, v0, v1);   // all 8 warps of a block share b
        sh_sec[0] = i0; sh_sec[1] = i1;
    }
    __syncthreads();
    int sec = sh_sec[r >> 8];
    int s = sec*WORDL + (r & 255);
    float cov = coverage[b*SLEN + s];
    const float4* ef  = (const float4*)(enc_feature + ((size_t)(b*SLEN + s))*DIM);
    const float4* df  = (const float4*)(g_decfeat + b*DIM);
    const float4* v4  = (const float4*)vvec;
    const float4* wc4 = (const float4*)w_cov;
    float acc = 0.f;
#pragma unroll
    for (int i = 0; i < 8; i++) {
        int kk = lane + i*32;
        float4 e  = __ldg(&ef[kk]);
        float4 dd = df[kk];
        float4 vv = __ldg(&v4[kk]);
        float4 wc = __ldg(&wc4[kk]);
        acc += vv.x * fast_tanh(fmaf(cov, wc.x, e.x + dd.x));
        acc += vv.y * fast_tanh(fmaf(cov, wc.y, e.y + dd.y));
        acc += vv.z * fast_tanh(fmaf(cov, wc.z, e.z + dd.z));
        acc += vv.w * fast_tanh(fmaf(cov, wc.w, e.w + dd.w));
    }
#pragma unroll
    for (int o = 16; o > 0; o >>= 1) acc += __shfl_xor_sync(0xffffffffu, acc, o);
    if (lane == 0) g_scores[b*GATH + r] = acc;
}

// ---------------- block reduce helper (512 threads) ----------------
__device__ __forceinline__ float blkred(float v, float* red, bool is_max) {
#pragma unroll
    for (int o = 16; o > 0; o >>= 1) {
        float t = __shfl_xor_sync(0xffffffffu, v, o);
        v = is_max ? fmaxf(v, t) : (v + t);
    }
    __syncthreads();
    if ((threadIdx.x & 31) == 0) red[threadIdx.x >> 5] = v;
    __syncthreads();
    if (threadIdx.x < 32) {
        float x = (threadIdx.x < 16) ? red[threadIdx.x]
                                     : (is_max ? -__int_as_float(0x7f800000) : 0.f);
#pragma unroll
        for (int o = 8; o > 0; o >>= 1) {
            float t = __shfl_xor_sync(0xffffffffu, x, o);
            x = is_max ? fmaxf(x, t) : (x + t);
        }
        if (threadIdx.x == 0) red[0] = x;
    }
    __syncthreads();
    return red[0];
}

// ---------------- K4: softmax (scale-invariant form) -> g_attn ----------------
__global__ __launch_bounds__(512) void k4_softmax(const float* __restrict__ enc_mask,
                                                  const float* __restrict__ focus) {
    __shared__ float red[16];
    __shared__ int   sh_sec[2];
    __shared__ float sh_tv[2];
    int b = blockIdx.x;
    int j = threadIdx.x;
    if (j == 0) {
        int i0, i1; float v0, v1;
        top2_focus(focus, b, i0, i1, v0, v1);
        sh_sec[0] = i0; sh_sec[1] = i1; sh_tv[0] = v0; sh_tv[1] = v1;
    }
    __syncthreads();
    int f = j >> 8;
    int s = sh_sec[f]*WORDL + (j & 255);
    float tv = sh_tv[f];
    float sc = g_scores[b*GATH + j];
    float m  = enc_mask[b*SLEN + s];

    float mx   = blkred(sc, red, true);
    float a0   = __expf(sc - mx) * m;          // e/Σe cancels against the renorm
    float sum2 = blkred(a0, red, false);
    float a1   = tv * (a0 / sum2);
    float sum3 = blkred(a1, red, false);
    g_attn[b*GATH + j] = a1 / sum3;
}

// ---------------- K5: context partials, float4 per thread, high MLP ----------------
// grid (2 d-chunks of 512, 16 b, 16 s-chunks of 32 rows), 128 threads
__global__ __launch_bounds__(128) void k5_ctx(const float* __restrict__ enc_output,
                                              const float* __restrict__ focus) {
    __shared__ float sh_a[32];
    __shared__ int sh_sec;
    int b  = blockIdx.y;
    int sc = blockIdx.z;            // 0..15
    int f  = sc >> 3;
    int w0 = (sc & 7) * 32;
    int d  = blockIdx.x*512 + threadIdx.x*4;
    if (threadIdx.x < 32)
        sh_a[threadIdx.x] = g_attn[b*GATH + f*WORDL + w0 + threadIdx.x];
    if (threadIdx.x == 32 || (blockDim.x <= 32 && threadIdx.x == 0)) { }
    if (threadIdx.x == 33) { }
    if (threadIdx.x == 0) {
        int i0, i1; float v0, v1;
        top2_focus(focus, b, i0, i1, v0, v1);
        sh_sec = f ? i1 : i0;
    }
    __syncthreads();
    const float4* base = (const float4*)(enc_output
        + ((size_t)(b*SLEN + sh_sec*WORDL + w0))*DIM) + (d >> 2);
    float4 a0 = make_float4(0,0,0,0), a1 = a0, a2 = a0, a3 = a0;
#pragma unroll
    for (int w = 0; w < 32; w += 4) {
        float4 r0 = __ldg(base + (size_t)(w+0)*(DIM/4));
        float4 r1 = __ldg(base + (size_t)(w+1)*(DIM/4));
        float4 r2 = __ldg(base + (size_t)(w+2)*(DIM/4));
        float4 r3 = __ldg(base + (size_t)(w+3)*(DIM/4));
        float c0 = sh_a[w], c1 = sh_a[w+1], c2 = sh_a[w+2], c3 = sh_a[w+3];
        a0.x = fmaf(c0, r0.x, a0.x); a0.y = fmaf(c0, r0.y, a0.y);
        a0.z = fmaf(c0, r0.z, a0.z); a0.w = fmaf(c0, r0.w, a0.w);
        a1.x = fmaf(c1, r1.x, a1.x); a1.y = fmaf(c1, r1.y, a1.y);
        a1.z = fmaf(c1, r1.z, a1.z); a1.w = fmaf(c1, r1.w, a1.w);
        a2.x = fmaf(c2, r2.x, a2.x); a2.y = fmaf(c2, r2.y, a2.y);
        a2.z = fmaf(c2, r2.z, a2.z); a2.w = fmaf(c2, r2.w, a2.w);
        a3.x = fmaf(c3, r3.x, a3.x); a3.y = fmaf(c3, r3.y, a3.y);
        a3.z = fmaf(c3, r3.z, a3.z); a3.w = fmaf(c3, r3.w, a3.w);
    }
    float4 s = make_float4((a0.x+a1.x)+(a2.x+a3.x), (a0.y+a1.y)+(a2.y+a3.y),
                           (a0.z+a1.z)+(a2.z+a3.z), (a0.w+a1.w)+(a2.w+a3.w));
    *(float4*)(g_ctxpart + ((size_t)(sc*NB + b))*DIM + d) = s;
}

// ---------------- K6: fused epilogue — context combine + wide scatter ----------------
// blocks [0,16): sum NPART context partials. blocks [16,80): attn_dist + coverage_out.
__global__ __launch_bounds__(256) void k6_epilogue(const float* __restrict__ coverage,
                                                   const float* __restrict__ focus,
                                                   float* __restrict__ out) {
    if (blockIdx.x < 16) {
        int i = blockIdx.x*256 + threadIdx.x;       // float4 index, 4096 total
        const float4* cp = (const float4*)g_ctxpart;
        float4 s = cp[i];
#pragma unroll
        for (int p = 1; p < NPART; p++) {
            float4 t = cp[p*(NB*DIM/4) + i];
            s.x += t.x; s.y += t.y; s.z += t.z; s.w += t.w;
        }
        ((float4*)out)[i] = s;
    } else {
        __shared__ int sh_i0, sh_i1;
        int gb = blockIdx.x - 16;                   // 64 blocks; 4 per batch
        int b  = gb >> 2;
        if (threadIdx.x == 0) {
            int i0, i1; float v0, v1;
            top2_focus(focus, b, i0, i1, v0, v1);
            sh_i0 = i0; sh_i1 = i1;
        }
        __syncthreads();
        int p4 = (gb & 3)*256 + threadIdx.x;        // float4 index within batch, 0..1023
        int pos = p4 << 2;
        int si = pos >> 8;
        int w  = pos & 255;
        float4 av = make_float4(0.f, 0.f, 0.f, 0.f);
        if (si == sh_i0)      av = *(const float4*)(g_attn + b*GATH + w);
        else if (si == sh_i1) av = *(const float4*)(g_attn + b*GATH + WORDL + w);
        float4 cv = __ldg((const float4*)(coverage + b*SLEN) + p4);
        float4* oa = (float4*)(out + NB*DIM + b*SLEN);
        float4* oc = (float4*)(out + NB*DIM + NB*SLEN + b*SLEN);
        oa[p4] = av;
        oc[p4] = make_float4(cv.x + av.x, cv.y + av.y, cv.z + av.z, cv.w + av.w);
    }
}

extern "C" void kernel_launch(void* const* d_in, const int* in_sizes, int n_in,
                              void* d_out, int out_size) {
    const float* dec_hidden  = (const float*)d_in[0];
    const float* enc_output  = (const float*)d_in[1];
    const float* enc_feature = (const float*)d_in[2];
    const float* enc_mask    = (const float*)d_in[3];
    // d_in[4] = sec_attn (unused by reference)
    const float* coverage    = (const float*)d_in[5];
    const float* focus       = (const float*)d_in[6];
    const float* W_dec       = (const float*)d_in[7];
    const float* b_dec       = (const float*)d_in[8];
    const float* vvec        = (const float*)d_in[9];
    const float* w_cov       = (const float*)d_in[10];
    float* out = (float*)d_out;

    k1_decproj<<<128, 256>>>(dec_hidden, W_dec, b_dec);
    k3_scores<<<1024, 256>>>(enc_feature, coverage, vvec, w_cov, focus);
    k4_softmax<<<16, 512>>>(enc_mask, focus);
    k5_ctx<<<dim3(2, 16, 16), 128>>>(enc_output, focus);
    k6_epilogue<<<80, 256>>>(coverage, focus, out);
}